// round 1
// baseline (speedup 1.0000x reference)
#include <cuda_runtime.h>

// Global accumulators (no device mallocs allowed).
__device__ float g_sums[5];
__device__ int   g_cnts[5];

__global__ void mcl_init_kernel() {
    if (threadIdx.x < 5) {
        g_sums[threadIdx.x] = 0.0f;
        g_cnts[threadIdx.x] = 0;
    }
}

__global__ void __launch_bounds__(256) mcl_main_kernel(
    const float* __restrict__ pre,
    const float* __restrict__ real,
    float* __restrict__ mask_out,   // d_out + 6
    int n4,                         // number of float4 groups
    int n)                          // total elements
{
    float ls0 = 0.f, ls1 = 0.f, ls2 = 0.f, ls3 = 0.f, ls4 = 0.f;
    int   lc0 = 0,   lc1 = 0,   lc2 = 0,   lc3 = 0,   lc4 = 0;

    const float4* __restrict__ p4 = reinterpret_cast<const float4*>(pre);
    const float4* __restrict__ r4 = reinterpret_cast<const float4*>(real);

    const int stride = gridDim.x * blockDim.x;
    for (int i = blockIdx.x * blockDim.x + threadIdx.x; i < n4; i += stride) {
        float4 p = p4[i];
        float4 r = r4[i];

        float pr[4] = {p.x, p.y, p.z, p.w};
        float rr[4] = {r.x, r.y, r.z, r.w};
        float om[4];

        #pragma unroll
        for (int k = 0; k < 4; k++) {
            float rv = rr[k];
            float d  = fabsf(pr[k] - rv);
            // Memberships are NOT exclusive: boundaries belong to two ranges,
            // and range 0 = [-1,1] covers all others. Compute independently.
            bool m0 = (rv >= -1.0f) && (rv <=  1.0f);
            bool m1 = (rv >= -1.0f) && (rv <= -0.5f);
            bool m2 = (rv >= -0.5f) && (rv <=  0.0f);
            bool m3 = (rv >=  0.0f) && (rv <=  0.5f);
            bool m4 = (rv >=  0.5f) && (rv <=  1.0f);

            ls0 += m0 ? d : 0.f;  lc0 += m0;
            ls1 += m1 ? d : 0.f;  lc1 += m1;
            ls2 += m2 ? d : 0.f;  lc2 += m2;
            ls3 += m3 ? d : 0.f;  lc3 += m3;
            ls4 += m4 ? d : 0.f;  lc4 += m4;

            // Last matching range wins (torch loop overwrite semantics).
            int cls = m4 ? 4 : (m3 ? 3 : (m2 ? 2 : (m1 ? 1 : 0)));
            om[k] = (float)cls * 0.5f - 1.0f;
        }

        // mask_out = d_out+6 -> 8B aligned; mask_out + 4*i keeps 8B alignment.
        float2* mo = reinterpret_cast<float2*>(mask_out + 4ull * (unsigned)i);
        mo[0] = make_float2(om[0], om[1]);
        mo[1] = make_float2(om[2], om[3]);
    }

    // Scalar tail (n % 4 != 0) handled by one thread.
    if (blockIdx.x == 0 && threadIdx.x == 0) {
        for (int j = 4 * n4; j < n; j++) {
            float rv = real[j];
            float d  = fabsf(pre[j] - rv);
            bool m0 = (rv >= -1.0f) && (rv <=  1.0f);
            bool m1 = (rv >= -1.0f) && (rv <= -0.5f);
            bool m2 = (rv >= -0.5f) && (rv <=  0.0f);
            bool m3 = (rv >=  0.0f) && (rv <=  0.5f);
            bool m4 = (rv >=  0.5f) && (rv <=  1.0f);
            ls0 += m0 ? d : 0.f;  lc0 += m0;
            ls1 += m1 ? d : 0.f;  lc1 += m1;
            ls2 += m2 ? d : 0.f;  lc2 += m2;
            ls3 += m3 ? d : 0.f;  lc3 += m3;
            ls4 += m4 ? d : 0.f;  lc4 += m4;
            int cls = m4 ? 4 : (m3 ? 3 : (m2 ? 2 : (m1 ? 1 : 0)));
            mask_out[j] = (float)cls * 0.5f - 1.0f;
        }
    }

    // ---- Reduction: warp shuffle -> shared -> per-block atomics ----
    float ws[5] = {ls0, ls1, ls2, ls3, ls4};
    int   wc[5] = {lc0, lc1, lc2, lc3, lc4};

    #pragma unroll
    for (int off = 16; off > 0; off >>= 1) {
        #pragma unroll
        for (int j = 0; j < 5; j++) {
            ws[j] += __shfl_down_sync(0xffffffffu, ws[j], off);
            wc[j] += __shfl_down_sync(0xffffffffu, wc[j], off);
        }
    }

    __shared__ float ss[5][8];
    __shared__ int   sc[5][8];
    int wid  = threadIdx.x >> 5;
    int lane = threadIdx.x & 31;
    if (lane == 0) {
        #pragma unroll
        for (int j = 0; j < 5; j++) { ss[j][wid] = ws[j]; sc[j][wid] = wc[j]; }
    }
    __syncthreads();

    if (wid == 0) {
        int nw = blockDim.x >> 5;
        #pragma unroll
        for (int j = 0; j < 5; j++) {
            float v = (lane < nw) ? ss[j][lane] : 0.f;
            int   c = (lane < nw) ? sc[j][lane] : 0;
            #pragma unroll
            for (int off = 4; off > 0; off >>= 1) {
                v += __shfl_down_sync(0xffffffffu, v, off);
                c += __shfl_down_sync(0xffffffffu, c, off);
            }
            if (lane == 0) {
                atomicAdd(&g_sums[j], v);
                atomicAdd(&g_cnts[j], c);
            }
        }
    }
}

__global__ void mcl_final_kernel(float* __restrict__ out) {
    if (threadIdx.x == 0 && blockIdx.x == 0) {
        float tot = 0.f;
        #pragma unroll
        for (int i = 0; i < 5; i++) {
            int c = g_cnts[i];
            int denom = c > 1 ? c : 1;
            float li = (c == 0) ? 0.f : (g_sums[i] / (float)denom) * 0.2f;
            out[1 + i] = li;
            tot += li;
        }
        out[0] = tot;
    }
}

extern "C" void kernel_launch(void* const* d_in, const int* in_sizes, int n_in,
                              void* d_out, int out_size) {
    const float* pre  = (const float*)d_in[0];
    const float* real = (const float*)d_in[1];
    float* out = (float*)d_out;

    int n  = in_sizes[0];
    int n4 = n >> 2;

    mcl_init_kernel<<<1, 32>>>();
    // 148 SMs * 4 CTAs -> grid-stride with good MLP, few atomics.
    mcl_main_kernel<<<592, 256>>>(pre, real, out + 6, n4, n);
    mcl_final_kernel<<<1, 32>>>(out);
}